// round 1
// baseline (speedup 1.0000x reference)
#include <cuda_runtime.h>
#include <math.h>

#define Bq  2
#define Sq  2048
#define Dq  1024
#define Hq  16
#define DKq 64
#define Mq  (Bq*Sq)   // 4096

// Scratch (allocation-free rule: __device__ globals). 4 x 16 MB.
__device__ float g_Q[(size_t)Mq*Dq];
__device__ float g_K[(size_t)Mq*Dq];
__device__ float g_V[(size_t)Mq*Dq];
__device__ float g_A[(size_t)Mq*Dq];

// ---------------------------------------------------------------------------
// C[M,N] = A[M,K] * W[N,K]^T + bias[N]      (both operands K-contiguous)
// 64x64 tile, BK=32, 256 threads, 4x4 microtile per thread.
// ---------------------------------------------------------------------------
__global__ __launch_bounds__(256) void gemm_bias(
    const float* __restrict__ A, const float* __restrict__ W,
    const float* __restrict__ bias, float* __restrict__ C,
    int M, int N, int K)
{
    __shared__ float As[32*65];
    __shared__ float Ws[32*65];
    const int bm = blockIdx.y*64, bn = blockIdx.x*64;
    const int tid = threadIdx.x;
    const int tr = tid>>4, tc = tid&15;
    const int lr = tid>>3;          // 0..31
    const int lc = (tid&7)*4;       // 0,4,...,28
    float acc[4][4] = {};

    for (int k0 = 0; k0 < K; k0 += 32) {
        #pragma unroll
        for (int p = 0; p < 2; p++) {
            int r = lr + p*32;
            float4 a = *(const float4*)(A + (size_t)(bm+r)*K + k0 + lc);
            As[(lc+0)*65+r]=a.x; As[(lc+1)*65+r]=a.y; As[(lc+2)*65+r]=a.z; As[(lc+3)*65+r]=a.w;
            float4 w = *(const float4*)(W + (size_t)(bn+r)*K + k0 + lc);
            Ws[(lc+0)*65+r]=w.x; Ws[(lc+1)*65+r]=w.y; Ws[(lc+2)*65+r]=w.z; Ws[(lc+3)*65+r]=w.w;
        }
        __syncthreads();
        #pragma unroll
        for (int k = 0; k < 32; k++) {
            float a[4], b[4];
            #pragma unroll
            for (int i = 0; i < 4; i++) a[i] = As[k*65 + tr*4+i];
            #pragma unroll
            for (int j = 0; j < 4; j++) b[j] = Ws[k*65 + tc*4+j];
            #pragma unroll
            for (int i = 0; i < 4; i++)
                #pragma unroll
                for (int j = 0; j < 4; j++)
                    acc[i][j] = fmaf(a[i], b[j], acc[i][j]);
        }
        __syncthreads();
    }
    float4 bb = *(const float4*)(bias + bn + tc*4);
    #pragma unroll
    for (int i = 0; i < 4; i++) {
        float4 o;
        o.x = acc[i][0]+bb.x; o.y = acc[i][1]+bb.y;
        o.z = acc[i][2]+bb.z; o.w = acc[i][3]+bb.w;
        *(float4*)(C + (size_t)(bm+tr*4+i)*N + bn + tc*4) = o;
    }
}

// ---------------------------------------------------------------------------
// Per-(b,s,h) RMSNorm over DK=64 + RoPE. One warp per row.
// Lane l owns elements (l, l+32) -> rotate_half is a register-pair op.
// blockIdx.y: 0 -> Q (qn_w), 1 -> K (kn_w)
// ---------------------------------------------------------------------------
__global__ __launch_bounds__(128) void norm_rope(
    float* __restrict__ Q, float* __restrict__ K,
    const float* __restrict__ cs, const float* __restrict__ sn,
    const float* __restrict__ qn, const float* __restrict__ kn)
{
    int w    = (blockIdx.x * blockDim.x + threadIdx.x) >> 5;  // row id in [0, Mq*Hq)
    int lane = threadIdx.x & 31;
    float*       X  = (blockIdx.y == 0) ? Q  : K;
    const float* wt = (blockIdx.y == 0) ? qn : kn;
    int bs = w >> 4, h = w & 15;
    int s  = bs & (Sq - 1);
    float* row = X + (size_t)bs*Dq + h*DKq;

    float x0 = row[lane], x1 = row[lane+32];
    float ss = x0*x0 + x1*x1;
    #pragma unroll
    for (int off = 16; off; off >>= 1) ss += __shfl_xor_sync(0xffffffffu, ss, off);
    float inv = rsqrtf(ss*(1.0f/64.0f) + 1e-6f);
    float y0 = x0*inv*wt[lane], y1 = x1*inv*wt[lane+32];

    const float* c  = cs + (size_t)s*DKq;
    const float* si = sn + (size_t)s*DKq;
    row[lane]    = y0*c[lane]    - y1*si[lane];     // x*cos + (-x2)*sin
    row[lane+32] = y1*c[lane+32] + y0*si[lane+32];  // x*cos + ( x1)*sin
}

// ---------------------------------------------------------------------------
// Flash attention, causal. CTA = (q-block of 64 rows) x (b,h).
// 64x64 K/V tiles, online softmax, only kb <= qb visited.
// Layout of Q/K/V/O: [b*S+s][h*64+dk] (same as projection output).
// ---------------------------------------------------------------------------
__global__ __launch_bounds__(256) void flash_attn(
    const float* __restrict__ Q, const float* __restrict__ K,
    const float* __restrict__ V, float* __restrict__ O)
{
    extern __shared__ float sm[];
    float* Qs = sm;              // 64*65
    float* Ks = Qs + 64*65;
    float* Vs = Ks + 64*65;
    float* Ps = Vs + 64*65;
    float* rscale = Ps + 64*65;  // 64
    float* rl     = rscale + 64; // 64

    const int qb = gridDim.x - 1 - blockIdx.x;   // heavy blocks first
    const int bh = blockIdx.y;
    const int b = bh >> 4, h = bh & 15;
    const int tid = threadIdx.x;
    const int tr = tid >> 4, tc = tid & 15;
    const size_t base = ((size_t)b*Sq)*Dq + h*DKq;
    const float* Qg = Q + base;
    const float* Kg = K + base;
    const float* Vg = V + base;

    // load Q tile (64x64)
    #pragma unroll
    for (int p = 0; p < 4; p++) {
        int r = (tid>>4) + p*16;
        int c = (tid&15)*4;
        float4 v = *(const float4*)(Qg + (size_t)(qb*64+r)*Dq + c);
        Qs[r*65+c]=v.x; Qs[r*65+c+1]=v.y; Qs[r*65+c+2]=v.z; Qs[r*65+c+3]=v.w;
    }

    float o[4][4] = {};
    float m_i = -INFINITY, l_i = 0.f;
    const int srow = tid >> 2, sseg = (tid & 3) * 16;

    for (int kb = 0; kb <= qb; kb++) {
        __syncthreads();  // previous PV reads done (and Q stores visible on iter 0)
        #pragma unroll
        for (int p = 0; p < 4; p++) {
            int r = (tid>>4) + p*16;
            int c = (tid&15)*4;
            float4 kv = *(const float4*)(Kg + (size_t)(kb*64+r)*Dq + c);
            Ks[r*65+c]=kv.x; Ks[r*65+c+1]=kv.y; Ks[r*65+c+2]=kv.z; Ks[r*65+c+3]=kv.w;
            float4 vv = *(const float4*)(Vg + (size_t)(kb*64+r)*Dq + c);
            Vs[r*65+c]=vv.x; Vs[r*65+c+1]=vv.y; Vs[r*65+c+2]=vv.z; Vs[r*65+c+3]=vv.w;
        }
        __syncthreads();

        // S = Q K^T (64x64x64)
        float acc[4][4] = {};
        #pragma unroll 8
        for (int k = 0; k < 64; k++) {
            float a[4], bv[4];
            #pragma unroll
            for (int i = 0; i < 4; i++) a[i]  = Qs[(tr*4+i)*65 + k];
            #pragma unroll
            for (int j = 0; j < 4; j++) bv[j] = Ks[(tc*4+j)*65 + k];
            #pragma unroll
            for (int i = 0; i < 4; i++)
                #pragma unroll
                for (int j = 0; j < 4; j++)
                    acc[i][j] = fmaf(a[i], bv[j], acc[i][j]);
        }
        const bool diag = (kb == qb);
        #pragma unroll
        for (int i = 0; i < 4; i++)
            #pragma unroll
            for (int j = 0; j < 4; j++) {
                float sv = acc[i][j] * 0.125f;   // 1/sqrt(64)
                if (diag && (tc*4+j) > (tr*4+i)) sv = -1e9f;
                Ps[(tr*4+i)*65 + tc*4+j] = sv;
            }
        __syncthreads();

        // online softmax: 4 threads per row (consecutive lanes)
        float pv[16]; float vmax = -INFINITY;
        #pragma unroll
        for (int c = 0; c < 16; c++) { pv[c] = Ps[srow*65 + sseg + c]; vmax = fmaxf(vmax, pv[c]); }
        vmax = fmaxf(vmax, __shfl_xor_sync(0xffffffffu, vmax, 1));
        vmax = fmaxf(vmax, __shfl_xor_sync(0xffffffffu, vmax, 2));
        float m_new = fmaxf(m_i, vmax);
        float scl = __expf(m_i - m_new);     // exp(-inf)=0 on first block
        float lsum = 0.f;
        #pragma unroll
        for (int c = 0; c < 16; c++) {
            float e = __expf(pv[c] - m_new);
            lsum += e;
            Ps[srow*65 + sseg + c] = e;
        }
        lsum += __shfl_xor_sync(0xffffffffu, lsum, 1);
        lsum += __shfl_xor_sync(0xffffffffu, lsum, 2);
        l_i = l_i*scl + lsum;
        m_i = m_new;
        if ((tid & 3) == 0) { rscale[srow] = scl; rl[srow] = l_i; }
        __syncthreads();

        // rescale O then O += P V
        #pragma unroll
        for (int i = 0; i < 4; i++) {
            float sc = rscale[tr*4+i];
            #pragma unroll
            for (int j = 0; j < 4; j++) o[i][j] *= sc;
        }
        #pragma unroll 8
        for (int k = 0; k < 64; k++) {
            float a[4], bv[4];
            #pragma unroll
            for (int i = 0; i < 4; i++) a[i]  = Ps[(tr*4+i)*65 + k];
            #pragma unroll
            for (int j = 0; j < 4; j++) bv[j] = Vs[k*65 + tc*4+j];
            #pragma unroll
            for (int i = 0; i < 4; i++)
                #pragma unroll
                for (int j = 0; j < 4; j++)
                    o[i][j] = fmaf(a[i], bv[j], o[i][j]);
        }
    }

    // epilogue: normalize and store into [b*S+s][h*64+dk]
    float* Og = O + base;
    #pragma unroll
    for (int i = 0; i < 4; i++) {
        float inv = 1.0f / rl[tr*4+i];
        #pragma unroll
        for (int j = 0; j < 4; j++)
            Og[(size_t)(qb*64 + tr*4+i)*Dq + tc*4+j] = o[i][j]*inv;
    }
}

// ---------------------------------------------------------------------------
extern "C" void kernel_launch(void* const* d_in, const int* in_sizes, int n_in,
                              void* d_out, int out_size)
{
    (void)in_sizes; (void)n_in; (void)out_size;
    const float* q  = (const float*)d_in[0];
    const float* k  = (const float*)d_in[1];
    const float* v  = (const float*)d_in[2];
    // d_in[3] = mask (tril, known causal) — unused
    const float* cs = (const float*)d_in[4];
    const float* sn = (const float*)d_in[5];
    const float* wq = (const float*)d_in[6];
    const float* bq = (const float*)d_in[7];
    const float* wk = (const float*)d_in[8];
    const float* bk = (const float*)d_in[9];
    const float* wv = (const float*)d_in[10];
    const float* bv = (const float*)d_in[11];
    const float* wo = (const float*)d_in[12];
    const float* bo = (const float*)d_in[13];
    const float* qn = (const float*)d_in[14];
    const float* kn = (const float*)d_in[15];
    float* out = (float*)d_out;

    float *pQ, *pK, *pV, *pA;
    cudaGetSymbolAddress((void**)&pQ, g_Q);
    cudaGetSymbolAddress((void**)&pK, g_K);
    cudaGetSymbolAddress((void**)&pV, g_V);
    cudaGetSymbolAddress((void**)&pA, g_A);

    dim3 gg(Dq/64, Mq/64);  // (16, 64)
    gemm_bias<<<gg, 256>>>(q, wq, bq, pQ, Mq, Dq, Dq);
    gemm_bias<<<gg, 256>>>(k, wk, bk, pK, Mq, Dq, Dq);
    gemm_bias<<<gg, 256>>>(v, wv, bv, pV, Mq, Dq, Dq);

    norm_rope<<<dim3(Mq*Hq/4, 2), 128>>>(pQ, pK, cs, sn, qn, kn);

    int smem = (4*64*65 + 128) * (int)sizeof(float);  // 67072 B
    cudaFuncSetAttribute(flash_attn, cudaFuncAttributeMaxDynamicSharedMemorySize, smem);
    flash_attn<<<dim3(Sq/64, Bq*Hq), 256, smem>>>(pQ, pK, pV, pA);

    gemm_bias<<<gg, 256>>>(pA, wo, bo, out, Mq, Dq, Dq);
}

// round 3
// speedup vs baseline: 1.7123x; 1.7123x over previous
#include <cuda_runtime.h>
#include <cuda_bf16.h>
#include <math.h>
#include <stdint.h>

#define Bq  2
#define Sq  2048
#define Dq  1024
#define Hq  16
#define DKq 64
#define Mq  (Bq*Sq)   // 4096

// Scratch (__device__ globals; no allocs allowed)
__device__ float g_Q[(size_t)Mq*Dq];
__device__ float g_K[(size_t)Mq*Dq];
__device__ float g_V[(size_t)Mq*Dq];
__device__ float g_A[(size_t)Mq*Dq];
__device__ __nv_bfloat16 g_actH[(size_t)Mq*Dq];
__device__ __nv_bfloat16 g_actL[(size_t)Mq*Dq];
__device__ __nv_bfloat16 g_wH[(size_t)Dq*Dq];
__device__ __nv_bfloat16 g_wL[(size_t)Dq*Dq];

// ---------------------------------------------------------------------------
// helpers
// ---------------------------------------------------------------------------
__device__ __forceinline__ uint32_t smem_u32(const void* p) {
    uint32_t a;
    asm("{ .reg .u64 t; cvta.to.shared.u64 t, %1; cvt.u32.u64 %0, t; }" : "=r"(a) : "l"(p));
    return a;
}
__device__ __forceinline__ void cpa16(uint32_t saddr, const void* g) {
    asm volatile("cp.async.ca.shared.global [%0], [%1], 16;" :: "r"(saddr), "l"(g));
}
__device__ __forceinline__ void ldsm4(uint32_t* r, uint32_t addr) {
    asm volatile("ldmatrix.sync.aligned.m8n8.x4.shared.b16 {%0,%1,%2,%3}, [%4];"
        : "=r"(r[0]), "=r"(r[1]), "=r"(r[2]), "=r"(r[3]) : "r"(addr));
}
__device__ __forceinline__ void mma_bf16(float* c, const uint32_t* a, const uint32_t* b) {
    asm volatile("mma.sync.aligned.m16n8k16.row.col.f32.bf16.bf16.f32 "
        "{%0,%1,%2,%3}, {%4,%5,%6,%7}, {%8,%9}, {%0,%1,%2,%3};"
        : "+f"(c[0]), "+f"(c[1]), "+f"(c[2]), "+f"(c[3])
        : "r"(a[0]), "r"(a[1]), "r"(a[2]), "r"(a[3]), "r"(b[0]), "r"(b[1]));
}

// ---------------------------------------------------------------------------
// fp32 -> bf16 hi/lo split (error-compensated)
// ---------------------------------------------------------------------------
__global__ __launch_bounds__(256) void split_bf16(
    const float* __restrict__ x, __nv_bfloat16* __restrict__ h,
    __nv_bfloat16* __restrict__ l, int n4)
{
    int i = blockIdx.x * blockDim.x + threadIdx.x;
    if (i >= n4) return;
    float4 v = ((const float4*)x)[i];
    __nv_bfloat16 h0 = __float2bfloat16(v.x), h1 = __float2bfloat16(v.y);
    __nv_bfloat16 h2 = __float2bfloat16(v.z), h3 = __float2bfloat16(v.w);
    __nv_bfloat16 l0 = __float2bfloat16(v.x - __bfloat162float(h0));
    __nv_bfloat16 l1 = __float2bfloat16(v.y - __bfloat162float(h1));
    __nv_bfloat16 l2 = __float2bfloat16(v.z - __bfloat162float(h2));
    __nv_bfloat16 l3 = __float2bfloat16(v.w - __bfloat162float(h3));
    ((__nv_bfloat162*)h)[2*i]   = __nv_bfloat162(h0, h1);
    ((__nv_bfloat162*)h)[2*i+1] = __nv_bfloat162(h2, h3);
    ((__nv_bfloat162*)l)[2*i]   = __nv_bfloat162(l0, l1);
    ((__nv_bfloat162*)l)[2*i+1] = __nv_bfloat162(l2, l3);
}

// ---------------------------------------------------------------------------
// Tensor-core GEMM via mma.sync: C[M,N] = A[M,K] @ W[N,K]^T + bias
// bf16 hi/lo 3-MMA compensation. 128x128 CTA tile, 8 warps (32x64 each),
// K-chunk 32, double-buffered cp.async.
// smem layout per stage (32KB): Ah | Al | Wh | Wl, each 128 rows x 64B,
// row r chunk c (16B units) stored at r*64 + ((c ^ ((r>>1)&3))<<4).
// ---------------------------------------------------------------------------
#define TILE8K 8192
#define STAGE_B 32768
__global__ __launch_bounds__(256) void gemm_tc(
    const __nv_bfloat16* __restrict__ Ah, const __nv_bfloat16* __restrict__ Al,
    const __nv_bfloat16* __restrict__ Wh, const __nv_bfloat16* __restrict__ Wl,
    const float* __restrict__ bias, float* __restrict__ C, int M, int N, int K)
{
    extern __shared__ __align__(1024) char sm[];
    const uint32_t sbase = smem_u32(sm);
    const int tid = threadIdx.x;
    const int wid = tid >> 5, lane = tid & 31;
    const int bm = blockIdx.y * 128, bn = blockIdx.x * 128;
    const int wm = (wid >> 1) * 32, wn = (wid & 1) * 64;

    const __nv_bfloat16* srcs[4] = {
        Ah + (size_t)bm * K, Al + (size_t)bm * K,
        Wh + (size_t)bn * K, Wl + (size_t)bn * K };

    // per-thread load coords: two 16B chunks per tile
    const int r0 = tid >> 2, c0 = tid & 3;          // chunks 0..255
    const int r1 = (tid + 256) >> 2, c1 = tid & 3;  // chunks 256..511

    const int nkc = K >> 5;   // 32-wide K chunks

    // ---- issue stage 0
    {
        const int kofs = 0;
        #pragma unroll
        for (int t = 0; t < 4; t++) {
            const char* s = (const char*)(srcs[t] + kofs);
            uint32_t db = sbase + t * TILE8K;
            cpa16(db + r0*64 + (((c0) ^ ((r0>>1)&3))<<4), s + (size_t)r0*(K*2) + c0*16);
            cpa16(db + r1*64 + (((c1) ^ ((r1>>1)&3))<<4), s + (size_t)r1*(K*2) + c1*16);
        }
        asm volatile("cp.async.commit_group;");
    }

    float acc[2][8][4] = {};
    const int lt  = lane >> 3;   // ldmatrix tile id
    const int lr8 = lane & 7;    // row within 8

    for (int kc = 0; kc < nkc; kc++) {
        const int buf = kc & 1;
        if (kc + 1 < nkc) {
            const int kofs = (kc + 1) << 5;
            const uint32_t stb = sbase + ((kc + 1) & 1) * STAGE_B;
            #pragma unroll
            for (int t = 0; t < 4; t++) {
                const char* s = (const char*)(srcs[t] + kofs);
                uint32_t db = stb + t * TILE8K;
                cpa16(db + r0*64 + (((c0) ^ ((r0>>1)&3))<<4), s + (size_t)r0*(K*2) + c0*16);
                cpa16(db + r1*64 + (((c1) ^ ((r1>>1)&3))<<4), s + (size_t)r1*(K*2) + c1*16);
            }
            asm volatile("cp.async.commit_group;");
            asm volatile("cp.async.wait_group 1;");
        } else {
            asm volatile("cp.async.wait_group 0;");
        }
        __syncthreads();

        const uint32_t abH = sbase + buf * STAGE_B;
        const uint32_t abL = abH + TILE8K;
        const uint32_t wbH = abH + 2 * TILE8K;
        const uint32_t wbL = abH + 3 * TILE8K;

        #pragma unroll
        for (int ka = 0; ka < 2; ka++) {          // k atoms (16 each)
            uint32_t aH[2][4], aL[2][4], bH[8][2], bL[8][2];
            #pragma unroll
            for (int ma = 0; ma < 2; ma++) {
                int row = wm + ma*16 + ((lt & 1) << 3) + lr8;
                int ch  = (ka << 1) + (lt >> 1);
                uint32_t off = (uint32_t)(row*64 + ((ch ^ ((row>>1)&3)) << 4));
                ldsm4(aH[ma], abH + off);
                ldsm4(aL[ma], abL + off);
            }
            #pragma unroll
            for (int nb = 0; nb < 4; nb++) {      // pairs of n-atoms
                int row = wn + nb*16 + ((lt >> 1) << 3) + lr8;
                int ch  = (ka << 1) + (lt & 1);
                uint32_t off = (uint32_t)(row*64 + ((ch ^ ((row>>1)&3)) << 4));
                uint32_t r[4];
                ldsm4(r, wbH + off);
                bH[2*nb][0]=r[0]; bH[2*nb][1]=r[1]; bH[2*nb+1][0]=r[2]; bH[2*nb+1][1]=r[3];
                ldsm4(r, wbL + off);
                bL[2*nb][0]=r[0]; bL[2*nb][1]=r[1]; bL[2*nb+1][0]=r[2]; bL[2*nb+1][1]=r[3];
            }
            #pragma unroll
            for (int ma = 0; ma < 2; ma++)
                #pragma unroll
                for (int na = 0; na < 8; na++) {
                    mma_bf16(acc[ma][na], aH[ma], bH[na]);
                    mma_bf16(acc[ma][na], aL[ma], bH[na]);
                    mma_bf16(acc[ma][na], aH[ma], bL[na]);
                }
        }
        __syncthreads();
    }

    // epilogue: c0,c1 at (row, col..col+1), c2,c3 at (row+8, ...)
    #pragma unroll
    for (int ma = 0; ma < 2; ma++) {
        int r = bm + wm + ma*16 + (lane >> 2);
        #pragma unroll
        for (int na = 0; na < 8; na++) {
            int col = bn + wn + na*8 + (lane & 3)*2;
            float2 b2 = *(const float2*)(bias + col);
            float2 v0 = { acc[ma][na][0] + b2.x, acc[ma][na][1] + b2.y };
            float2 v1 = { acc[ma][na][2] + b2.x, acc[ma][na][3] + b2.y };
            *(float2*)(C + (size_t)r * N + col)       = v0;
            *(float2*)(C + (size_t)(r + 8) * N + col) = v1;
        }
    }
}

// ---------------------------------------------------------------------------
// Per-(b,s,h) RMSNorm over DK=64 + RoPE. One warp per row.
// ---------------------------------------------------------------------------
__global__ __launch_bounds__(128) void norm_rope(
    float* __restrict__ Q, float* __restrict__ K,
    const float* __restrict__ cs, const float* __restrict__ sn,
    const float* __restrict__ qn, const float* __restrict__ kn)
{
    int w    = (blockIdx.x * blockDim.x + threadIdx.x) >> 5;
    int lane = threadIdx.x & 31;
    float*       X  = (blockIdx.y == 0) ? Q  : K;
    const float* wt = (blockIdx.y == 0) ? qn : kn;
    int bs = w >> 4, h = w & 15;
    int s  = bs & (Sq - 1);
    float* row = X + (size_t)bs*Dq + h*DKq;

    float x0 = row[lane], x1 = row[lane+32];
    float ss = x0*x0 + x1*x1;
    #pragma unroll
    for (int off = 16; off; off >>= 1) ss += __shfl_xor_sync(0xffffffffu, ss, off);
    float inv = rsqrtf(ss*(1.0f/64.0f) + 1e-6f);
    float y0 = x0*inv*wt[lane], y1 = x1*inv*wt[lane+32];

    const float* c  = cs + (size_t)s*DKq;
    const float* si = sn + (size_t)s*DKq;
    row[lane]    = y0*c[lane]    - y1*si[lane];
    row[lane+32] = y1*c[lane+32] + y0*si[lane+32];
}

// ---------------------------------------------------------------------------
// Flash attention, causal, fp32 SIMT
// ---------------------------------------------------------------------------
__global__ __launch_bounds__(256) void flash_attn(
    const float* __restrict__ Q, const float* __restrict__ K,
    const float* __restrict__ V, float* __restrict__ O)
{
    extern __shared__ float smf[];
    float* Qs = smf;
    float* Ks = Qs + 64*65;
    float* Vs = Ks + 64*65;
    float* Ps = Vs + 64*65;
    float* rscale = Ps + 64*65;
    float* rl     = rscale + 64;

    const int qb = gridDim.x - 1 - blockIdx.x;
    const int bh = blockIdx.y;
    const int b = bh >> 4, h = bh & 15;
    const int tid = threadIdx.x;
    const int tr = tid >> 4, tc = tid & 15;
    const size_t base = ((size_t)b*Sq)*Dq + h*DKq;
    const float* Qg = Q + base;
    const float* Kg = K + base;
    const float* Vg = V + base;

    #pragma unroll
    for (int p = 0; p < 4; p++) {
        int r = (tid>>4) + p*16;
        int c = (tid&15)*4;
        float4 v = *(const float4*)(Qg + (size_t)(qb*64+r)*Dq + c);
        Qs[r*65+c]=v.x; Qs[r*65+c+1]=v.y; Qs[r*65+c+2]=v.z; Qs[r*65+c+3]=v.w;
    }

    float o[4][4] = {};
    float m_i = -INFINITY, l_i = 0.f;
    const int srow = tid >> 2, sseg = (tid & 3) * 16;

    for (int kb = 0; kb <= qb; kb++) {
        __syncthreads();
        #pragma unroll
        for (int p = 0; p < 4; p++) {
            int r = (tid>>4) + p*16;
            int c = (tid&15)*4;
            float4 kv = *(const float4*)(Kg + (size_t)(kb*64+r)*Dq + c);
            Ks[r*65+c]=kv.x; Ks[r*65+c+1]=kv.y; Ks[r*65+c+2]=kv.z; Ks[r*65+c+3]=kv.w;
            float4 vv = *(const float4*)(Vg + (size_t)(kb*64+r)*Dq + c);
            Vs[r*65+c]=vv.x; Vs[r*65+c+1]=vv.y; Vs[r*65+c+2]=vv.z; Vs[r*65+c+3]=vv.w;
        }
        __syncthreads();

        float acc[4][4] = {};
        #pragma unroll 8
        for (int k = 0; k < 64; k++) {
            float a[4], bv[4];
            #pragma unroll
            for (int i = 0; i < 4; i++) a[i]  = Qs[(tr*4+i)*65 + k];
            #pragma unroll
            for (int j = 0; j < 4; j++) bv[j] = Ks[(tc*4+j)*65 + k];
            #pragma unroll
            for (int i = 0; i < 4; i++)
                #pragma unroll
                for (int j = 0; j < 4; j++)
                    acc[i][j] = fmaf(a[i], bv[j], acc[i][j]);
        }
        const bool diag = (kb == qb);
        #pragma unroll
        for (int i = 0; i < 4; i++)
            #pragma unroll
            for (int j = 0; j < 4; j++) {
                float sv = acc[i][j] * 0.125f;
                if (diag && (tc*4+j) > (tr*4+i)) sv = -1e9f;
                Ps[(tr*4+i)*65 + tc*4+j] = sv;
            }
        __syncthreads();

        float pv[16]; float vmax = -INFINITY;
        #pragma unroll
        for (int c = 0; c < 16; c++) { pv[c] = Ps[srow*65 + sseg + c]; vmax = fmaxf(vmax, pv[c]); }
        vmax = fmaxf(vmax, __shfl_xor_sync(0xffffffffu, vmax, 1));
        vmax = fmaxf(vmax, __shfl_xor_sync(0xffffffffu, vmax, 2));
        float m_new = fmaxf(m_i, vmax);
        float scl = __expf(m_i - m_new);
        float lsum = 0.f;
        #pragma unroll
        for (int c = 0; c < 16; c++) {
            float e = __expf(pv[c] - m_new);
            lsum += e;
            Ps[srow*65 + sseg + c] = e;
        }
        lsum += __shfl_xor_sync(0xffffffffu, lsum, 1);
        lsum += __shfl_xor_sync(0xffffffffu, lsum, 2);
        l_i = l_i*scl + lsum;
        m_i = m_new;
        if ((tid & 3) == 0) { rscale[srow] = scl; rl[srow] = l_i; }
        __syncthreads();

        #pragma unroll
        for (int i = 0; i < 4; i++) {
            float sc = rscale[tr*4+i];
            #pragma unroll
            for (int j = 0; j < 4; j++) o[i][j] *= sc;
        }
        #pragma unroll 8
        for (int k = 0; k < 64; k++) {
            float a[4], bv[4];
            #pragma unroll
            for (int i = 0; i < 4; i++) a[i]  = Ps[(tr*4+i)*65 + k];
            #pragma unroll
            for (int j = 0; j < 4; j++) bv[j] = Vs[k*65 + tc*4+j];
            #pragma unroll
            for (int i = 0; i < 4; i++)
                #pragma unroll
                for (int j = 0; j < 4; j++)
                    o[i][j] = fmaf(a[i], bv[j], o[i][j]);
        }
    }

    float* Og = O + base;
    #pragma unroll
    for (int i = 0; i < 4; i++) {
        float inv = 1.0f / rl[tr*4+i];
        #pragma unroll
        for (int j = 0; j < 4; j++)
            Og[(size_t)(qb*64 + tr*4+i)*Dq + tc*4+j] = o[i][j]*inv;
    }
}

// ---------------------------------------------------------------------------
extern "C" void kernel_launch(void* const* d_in, const int* in_sizes, int n_in,
                              void* d_out, int out_size)
{
    (void)in_sizes; (void)n_in; (void)out_size;
    const float* q  = (const float*)d_in[0];
    const float* k  = (const float*)d_in[1];
    const float* v  = (const float*)d_in[2];
    const float* cs = (const float*)d_in[4];
    const float* sn = (const float*)d_in[5];
    const float* wq = (const float*)d_in[6];
    const float* bq = (const float*)d_in[7];
    const float* wk = (const float*)d_in[8];
    const float* bk = (const float*)d_in[9];
    const float* wv = (const float*)d_in[10];
    const float* bv = (const float*)d_in[11];
    const float* wo = (const float*)d_in[12];
    const float* bo = (const float*)d_in[13];
    const float* qn = (const float*)d_in[14];
    const float* kn = (const float*)d_in[15];
    float* out = (float*)d_out;

    float *pQ, *pK, *pV, *pA;
    __nv_bfloat16 *aH, *aL, *wH, *wL;
    cudaGetSymbolAddress((void**)&pQ, g_Q);
    cudaGetSymbolAddress((void**)&pK, g_K);
    cudaGetSymbolAddress((void**)&pV, g_V);
    cudaGetSymbolAddress((void**)&pA, g_A);
    cudaGetSymbolAddress((void**)&aH, g_actH);
    cudaGetSymbolAddress((void**)&aL, g_actL);
    cudaGetSymbolAddress((void**)&wH, g_wH);
    cudaGetSymbolAddress((void**)&wL, g_wL);

    const int actN4 = Mq*Dq/4, wN4 = Dq*Dq/4;
    const int gsm = 2 * STAGE_B;                       // 65536
    const int asm_ = (4*64*65 + 128) * (int)sizeof(float);
    cudaFuncSetAttribute(gemm_tc, cudaFuncAttributeMaxDynamicSharedMemorySize, gsm);
    cudaFuncSetAttribute(flash_attn, cudaFuncAttributeMaxDynamicSharedMemorySize, asm_);

    dim3 gg(Dq/128, Mq/128);  // (8, 32)

    split_bf16<<<actN4/256, 256>>>(q, aH, aL, actN4);
    split_bf16<<<wN4/256, 256>>>(wq, wH, wL, wN4);
    gemm_tc<<<gg, 256, gsm>>>(aH, aL, wH, wL, bq, pQ, Mq, Dq, Dq);

    split_bf16<<<actN4/256, 256>>>(k, aH, aL, actN4);
    split_bf16<<<wN4/256, 256>>>(wk, wH, wL, wN4);
    gemm_tc<<<gg, 256, gsm>>>(aH, aL, wH, wL, bk, pK, Mq, Dq, Dq);

    split_bf16<<<actN4/256, 256>>>(v, aH, aL, actN4);
    split_bf16<<<wN4/256, 256>>>(wv, wH, wL, wN4);
    gemm_tc<<<gg, 256, gsm>>>(aH, aL, wH, wL, bv, pV, Mq, Dq, Dq);

    norm_rope<<<dim3(Mq*Hq/4, 2), 128>>>(pQ, pK, cs, sn, qn, kn);

    flash_attn<<<dim3(Sq/64, Bq*Hq), 256, asm_>>>(pQ, pK, pV, pA);

    split_bf16<<<actN4/256, 256>>>(pA, aH, aL, actN4);
    split_bf16<<<wN4/256, 256>>>(wo, wH, wL, wN4);
    gemm_tc<<<gg, 256, gsm>>>(aH, aL, wH, wL, bo, out, Mq, Dq, Dq);
}

// round 4
// speedup vs baseline: 3.1206x; 1.8224x over previous
#include <cuda_runtime.h>
#include <cuda_bf16.h>
#include <math.h>
#include <stdint.h>

#define Bq  2
#define Sq  2048
#define Dq  1024
#define Hq  16
#define DKq 64
#define Mq  (Bq*Sq)   // 4096

// Scratch (__device__ globals; no allocs allowed)
__device__ float g_Q[(size_t)Mq*Dq];
__device__ float g_K[(size_t)Mq*Dq];
__device__ float g_V[(size_t)Mq*Dq];
__device__ __nv_bfloat16 g_actH[(size_t)Mq*Dq];
__device__ __nv_bfloat16 g_actL[(size_t)Mq*Dq];
__device__ __nv_bfloat16 g_wH[(size_t)Dq*Dq];
__device__ __nv_bfloat16 g_wL[(size_t)Dq*Dq];
// head-major [b*16+h][s][64] bf16
__device__ __nv_bfloat16 g_Qh[(size_t)Mq*Dq];
__device__ __nv_bfloat16 g_Ql[(size_t)Mq*Dq];
__device__ __nv_bfloat16 g_Kh[(size_t)Mq*Dq];
__device__ __nv_bfloat16 g_Kl[(size_t)Mq*Dq];
__device__ __nv_bfloat16 g_Vh[(size_t)Mq*Dq];
__device__ __nv_bfloat16 g_Vl[(size_t)Mq*Dq];

// ---------------------------------------------------------------------------
// helpers
// ---------------------------------------------------------------------------
__device__ __forceinline__ uint32_t smem_u32(const void* p) {
    uint32_t a;
    asm("{ .reg .u64 t; cvta.to.shared.u64 t, %1; cvt.u32.u64 %0, t; }" : "=r"(a) : "l"(p));
    return a;
}
__device__ __forceinline__ void cpa16(uint32_t saddr, const void* g) {
    asm volatile("cp.async.ca.shared.global [%0], [%1], 16;" :: "r"(saddr), "l"(g));
}
__device__ __forceinline__ void ldsm4(uint32_t* r, uint32_t addr) {
    asm volatile("ldmatrix.sync.aligned.m8n8.x4.shared.b16 {%0,%1,%2,%3}, [%4];"
        : "=r"(r[0]), "=r"(r[1]), "=r"(r[2]), "=r"(r[3]) : "r"(addr));
}
__device__ __forceinline__ void ldsm4t(uint32_t* r, uint32_t addr) {
    asm volatile("ldmatrix.sync.aligned.m8n8.x4.trans.shared.b16 {%0,%1,%2,%3}, [%4];"
        : "=r"(r[0]), "=r"(r[1]), "=r"(r[2]), "=r"(r[3]) : "r"(addr));
}
__device__ __forceinline__ void mma_bf16(float* c, const uint32_t* a, const uint32_t* b) {
    asm volatile("mma.sync.aligned.m16n8k16.row.col.f32.bf16.bf16.f32 "
        "{%0,%1,%2,%3}, {%4,%5,%6,%7}, {%8,%9}, {%0,%1,%2,%3};"
        : "+f"(c[0]), "+f"(c[1]), "+f"(c[2]), "+f"(c[3])
        : "r"(a[0]), "r"(a[1]), "r"(a[2]), "r"(a[3]), "r"(b[0]), "r"(b[1]));
}
__device__ __forceinline__ uint32_t pack_bf2(float lo, float hi) {
    __nv_bfloat162 t = __floats2bfloat162_rn(lo, hi);
    return *(uint32_t*)&t;
}

// ---------------------------------------------------------------------------
// fp32 -> bf16 hi/lo split (error-compensated)
// ---------------------------------------------------------------------------
__global__ __launch_bounds__(256) void split_bf16(
    const float* __restrict__ x, __nv_bfloat16* __restrict__ h,
    __nv_bfloat16* __restrict__ l, int n4)
{
    int i = blockIdx.x * blockDim.x + threadIdx.x;
    if (i >= n4) return;
    float4 v = ((const float4*)x)[i];
    __nv_bfloat16 h0 = __float2bfloat16(v.x), h1 = __float2bfloat16(v.y);
    __nv_bfloat16 h2 = __float2bfloat16(v.z), h3 = __float2bfloat16(v.w);
    __nv_bfloat16 l0 = __float2bfloat16(v.x - __bfloat162float(h0));
    __nv_bfloat16 l1 = __float2bfloat16(v.y - __bfloat162float(h1));
    __nv_bfloat16 l2 = __float2bfloat16(v.z - __bfloat162float(h2));
    __nv_bfloat16 l3 = __float2bfloat16(v.w - __bfloat162float(h3));
    ((__nv_bfloat162*)h)[2*i]   = __nv_bfloat162(h0, h1);
    ((__nv_bfloat162*)h)[2*i+1] = __nv_bfloat162(h2, h3);
    ((__nv_bfloat162*)l)[2*i]   = __nv_bfloat162(l0, l1);
    ((__nv_bfloat162*)l)[2*i+1] = __nv_bfloat162(l2, l3);
}

// ---------------------------------------------------------------------------
// Tensor-core GEMM via mma.sync (unchanged from R3)
// ---------------------------------------------------------------------------
#define TILE8K 8192
#define STAGE_B 32768
__global__ __launch_bounds__(256) void gemm_tc(
    const __nv_bfloat16* __restrict__ Ah, const __nv_bfloat16* __restrict__ Al,
    const __nv_bfloat16* __restrict__ Wh, const __nv_bfloat16* __restrict__ Wl,
    const float* __restrict__ bias, float* __restrict__ C, int M, int N, int K)
{
    extern __shared__ __align__(1024) char sm[];
    const uint32_t sbase = smem_u32(sm);
    const int tid = threadIdx.x;
    const int wid = tid >> 5, lane = tid & 31;
    const int bm = blockIdx.y * 128, bn = blockIdx.x * 128;
    const int wm = (wid >> 1) * 32, wn = (wid & 1) * 64;

    const __nv_bfloat16* srcs[4] = {
        Ah + (size_t)bm * K, Al + (size_t)bm * K,
        Wh + (size_t)bn * K, Wl + (size_t)bn * K };

    const int r0 = tid >> 2, c0 = tid & 3;
    const int r1 = (tid + 256) >> 2, c1 = tid & 3;
    const int nkc = K >> 5;

    {
        #pragma unroll
        for (int t = 0; t < 4; t++) {
            const char* s = (const char*)(srcs[t]);
            uint32_t db = sbase + t * TILE8K;
            cpa16(db + r0*64 + (((c0) ^ ((r0>>1)&3))<<4), s + (size_t)r0*(K*2) + c0*16);
            cpa16(db + r1*64 + (((c1) ^ ((r1>>1)&3))<<4), s + (size_t)r1*(K*2) + c1*16);
        }
        asm volatile("cp.async.commit_group;");
    }

    float acc[2][8][4] = {};
    const int lt  = lane >> 3;
    const int lr8 = lane & 7;

    for (int kc = 0; kc < nkc; kc++) {
        const int buf = kc & 1;
        if (kc + 1 < nkc) {
            const int kofs = (kc + 1) << 5;
            const uint32_t stb = sbase + ((kc + 1) & 1) * STAGE_B;
            #pragma unroll
            for (int t = 0; t < 4; t++) {
                const char* s = (const char*)(srcs[t] + kofs);
                uint32_t db = stb + t * TILE8K;
                cpa16(db + r0*64 + (((c0) ^ ((r0>>1)&3))<<4), s + (size_t)r0*(K*2) + c0*16);
                cpa16(db + r1*64 + (((c1) ^ ((r1>>1)&3))<<4), s + (size_t)r1*(K*2) + c1*16);
            }
            asm volatile("cp.async.commit_group;");
            asm volatile("cp.async.wait_group 1;");
        } else {
            asm volatile("cp.async.wait_group 0;");
        }
        __syncthreads();

        const uint32_t abH = sbase + buf * STAGE_B;
        const uint32_t abL = abH + TILE8K;
        const uint32_t wbH = abH + 2 * TILE8K;
        const uint32_t wbL = abH + 3 * TILE8K;

        #pragma unroll
        for (int ka = 0; ka < 2; ka++) {
            uint32_t aH[2][4], aL[2][4], bH[8][2], bL[8][2];
            #pragma unroll
            for (int ma = 0; ma < 2; ma++) {
                int row = wm + ma*16 + ((lt & 1) << 3) + lr8;
                int ch  = (ka << 1) + (lt >> 1);
                uint32_t off = (uint32_t)(row*64 + ((ch ^ ((row>>1)&3)) << 4));
                ldsm4(aH[ma], abH + off);
                ldsm4(aL[ma], abL + off);
            }
            #pragma unroll
            for (int nb = 0; nb < 4; nb++) {
                int row = wn + nb*16 + ((lt >> 1) << 3) + lr8;
                int ch  = (ka << 1) + (lt & 1);
                uint32_t off = (uint32_t)(row*64 + ((ch ^ ((row>>1)&3)) << 4));
                uint32_t r[4];
                ldsm4(r, wbH + off);
                bH[2*nb][0]=r[0]; bH[2*nb][1]=r[1]; bH[2*nb+1][0]=r[2]; bH[2*nb+1][1]=r[3];
                ldsm4(r, wbL + off);
                bL[2*nb][0]=r[0]; bL[2*nb][1]=r[1]; bL[2*nb+1][0]=r[2]; bL[2*nb+1][1]=r[3];
            }
            #pragma unroll
            for (int ma = 0; ma < 2; ma++)
                #pragma unroll
                for (int na = 0; na < 8; na++) {
                    mma_bf16(acc[ma][na], aH[ma], bH[na]);
                    mma_bf16(acc[ma][na], aL[ma], bH[na]);
                    mma_bf16(acc[ma][na], aH[ma], bL[na]);
                }
        }
        __syncthreads();
    }

    #pragma unroll
    for (int ma = 0; ma < 2; ma++) {
        int r = bm + wm + ma*16 + (lane >> 2);
        #pragma unroll
        for (int na = 0; na < 8; na++) {
            int col = bn + wn + na*8 + (lane & 3)*2;
            float2 b2 = *(const float2*)(bias + col);
            float2 v0 = { acc[ma][na][0] + b2.x, acc[ma][na][1] + b2.y };
            float2 v1 = { acc[ma][na][2] + b2.x, acc[ma][na][3] + b2.y };
            *(float2*)(C + (size_t)r * N + col)       = v0;
            *(float2*)(C + (size_t)(r + 8) * N + col) = v1;
        }
    }
}

// ---------------------------------------------------------------------------
// RMSNorm + RoPE, writes bf16 hi/lo head-major [bh][s][64]
// ---------------------------------------------------------------------------
__global__ __launch_bounds__(128) void norm_rope_split(
    const float* __restrict__ Qin, const float* __restrict__ Kin,
    __nv_bfloat16* __restrict__ Qh, __nv_bfloat16* __restrict__ Ql,
    __nv_bfloat16* __restrict__ Kh, __nv_bfloat16* __restrict__ Kl,
    const float* __restrict__ cs, const float* __restrict__ sn,
    const float* __restrict__ qn, const float* __restrict__ kn)
{
    int w    = (blockIdx.x * blockDim.x + threadIdx.x) >> 5;
    int lane = threadIdx.x & 31;
    const float* Xin = (blockIdx.y == 0) ? Qin : Kin;
    const float* wt  = (blockIdx.y == 0) ? qn  : kn;
    __nv_bfloat16* OH = (blockIdx.y == 0) ? Qh : Kh;
    __nv_bfloat16* OL = (blockIdx.y == 0) ? Ql : Kl;
    int bs = w >> 4, h = w & 15;
    int b = bs >> 11, s = bs & (Sq - 1);
    const float* row = Xin + (size_t)bs*Dq + h*DKq;

    float x0 = row[lane], x1 = row[lane+32];
    float ss = x0*x0 + x1*x1;
    #pragma unroll
    for (int off = 16; off; off >>= 1) ss += __shfl_xor_sync(0xffffffffu, ss, off);
    float inv = rsqrtf(ss*(1.0f/64.0f) + 1e-6f);
    float y0 = x0*inv*wt[lane], y1 = x1*inv*wt[lane+32];

    const float* c  = cs + (size_t)s*DKq;
    const float* si = sn + (size_t)s*DKq;
    float r0 = y0*c[lane]    - y1*si[lane];
    float r1 = y1*c[lane+32] + y0*si[lane+32];

    size_t ob = ((size_t)(b*16 + h)*Sq + s)*DKq;
    __nv_bfloat16 h0 = __float2bfloat16(r0);
    __nv_bfloat16 h1 = __float2bfloat16(r1);
    OH[ob + lane]      = h0;
    OH[ob + lane + 32] = h1;
    OL[ob + lane]      = __float2bfloat16(r0 - __bfloat162float(h0));
    OL[ob + lane + 32] = __float2bfloat16(r1 - __bfloat162float(h1));
}

// ---------------------------------------------------------------------------
// V: fp32 [bs][h*64+d] -> bf16 hi/lo head-major
// ---------------------------------------------------------------------------
__global__ __launch_bounds__(256) void v_split(
    const float* __restrict__ V, __nv_bfloat16* __restrict__ Vh,
    __nv_bfloat16* __restrict__ Vl)
{
    int i = blockIdx.x * blockDim.x + threadIdx.x;   // float4 index
    float4 v = ((const float4*)V)[i];
    int bs = i >> 8, c4 = i & 255;
    int h = c4 >> 4, d = (c4 & 15) * 4;
    int b = bs >> 11, s = bs & (Sq - 1);
    size_t o = ((size_t)(b*16 + h)*Sq + s)*DKq + d;
    __nv_bfloat16 h0 = __float2bfloat16(v.x), h1 = __float2bfloat16(v.y);
    __nv_bfloat16 h2 = __float2bfloat16(v.z), h3 = __float2bfloat16(v.w);
    *(__nv_bfloat162*)(Vh + o)     = __nv_bfloat162(h0, h1);
    *(__nv_bfloat162*)(Vh + o + 2) = __nv_bfloat162(h2, h3);
    *(__nv_bfloat162*)(Vl + o)     = __nv_bfloat162(
        __float2bfloat16(v.x - __bfloat162float(h0)),
        __float2bfloat16(v.y - __bfloat162float(h1)));
    *(__nv_bfloat162*)(Vl + o + 2) = __nv_bfloat162(
        __float2bfloat16(v.z - __bfloat162float(h2)),
        __float2bfloat16(v.w - __bfloat162float(h3)));
}

// ---------------------------------------------------------------------------
// Flash attention, causal, bf16 mma.sync with hi/lo compensation.
// CTA: 128 q-rows x one (b,h). 8 warps, 16 rows each. KV tiles 64.
// smem: Qh|Ql (2x16KB) + 2 stages x (Kh|Kl|Vh|Vl) (4x8KB each).
// Swizzle (128B rows): off = r*128 + ((c ^ (r&7))<<4), c = 16B chunk 0..7.
// ---------------------------------------------------------------------------
#define ATT_SMEM (32768 + 2*32768)
__global__ __launch_bounds__(256, 2) void flash_attn_tc(
    const __nv_bfloat16* __restrict__ Qh, const __nv_bfloat16* __restrict__ Ql,
    const __nv_bfloat16* __restrict__ Kh, const __nv_bfloat16* __restrict__ Kl,
    const __nv_bfloat16* __restrict__ Vh, const __nv_bfloat16* __restrict__ Vl,
    __nv_bfloat16* __restrict__ Oh, __nv_bfloat16* __restrict__ Ol)
{
    extern __shared__ __align__(1024) char sm[];
    const uint32_t sQ = smem_u32(sm);            // Qh 16K | Ql 16K
    const uint32_t sStage = sQ + 32768;          // 2 x 32K
    const int tid = threadIdx.x, wid = tid >> 5, lane = tid & 31;
    const int qb = gridDim.x - 1 - blockIdx.x;
    const int bh = blockIdx.y;
    const int q0 = qb * 128;
    const size_t hb = (size_t)bh * Sq * DKq;

    const char* gQh = (const char*)(Qh + hb + (size_t)q0*64);
    const char* gQl = (const char*)(Ql + hb + (size_t)q0*64);
    const char* gKh = (const char*)(Kh + hb);
    const char* gKl = (const char*)(Kl + hb);
    const char* gVh = (const char*)(Vh + hb);
    const char* gVl = (const char*)(Vl + hb);

    const int nkb = 2*qb + 2;

    // ---- prologue: Q (hi/lo) + KV stage 0
    #pragma unroll
    for (int j = 0; j < 4; j++) {
        int i = tid + j*256;          // 1024 chunks per 128x64 tile
        int r = i >> 3, c = i & 7;
        uint32_t so = (uint32_t)(r*128 + ((c ^ (r&7)) << 4));
        cpa16(sQ + so,         gQh + r*128 + c*16);
        cpa16(sQ + 16384 + so, gQl + r*128 + c*16);
    }
    {
        const char* gs[4] = { gKh, gKl, gVh, gVl };
        #pragma unroll
        for (int t = 0; t < 4; t++)
            #pragma unroll
            for (int j = 0; j < 2; j++) {
                int i = tid + j*256;  // 512 chunks per 64x64 tile
                int r = i >> 3, c = i & 7;
                uint32_t so = (uint32_t)(r*128 + ((c ^ (r&7)) << 4));
                cpa16(sStage + t*8192 + so, gs[t] + r*128 + c*16);
            }
    }
    asm volatile("cp.async.commit_group;");

    float o[8][4] = {};
    float S[8][4];
    float m0 = -INFINITY, m1 = -INFINITY, l0 = 0.f, l1 = 0.f;
    uint32_t qfh[4][4];

    const int lg = lane >> 2;        // groupID (row within 16-strip)
    const int tg = lane & 3;         // thread-in-group
    // ldmatrix lane addressing helpers
    const int lrow = (((lane >> 3) & 1) << 3) + (lane & 7);
    const int lsel = lane >> 4;      // 0: first chunk, 1: second

    for (int kb = 0; kb < nkb; kb++) {
        if (kb + 1 < nkb) {
            const uint32_t stb = sStage + ((kb+1) & 1) * 32768;
            const int kvr = (kb+1) * 64;
            const char* gs[4] = { gKh, gKl, gVh, gVl };
            #pragma unroll
            for (int t = 0; t < 4; t++)
                #pragma unroll
                for (int j = 0; j < 2; j++) {
                    int i = tid + j*256;
                    int r = i >> 3, c = i & 7;
                    uint32_t so = (uint32_t)(r*128 + ((c ^ (r&7)) << 4));
                    cpa16(stb + t*8192 + so, gs[t] + (size_t)(kvr + r)*128 + c*16);
                }
            asm volatile("cp.async.commit_group;");
            asm volatile("cp.async.wait_group 1;");
        } else {
            asm volatile("cp.async.wait_group 0;");
        }
        __syncthreads();

        if (kb == 0) {
            // load resident Qh fragments (per k-atom)
            #pragma unroll
            for (int ka = 0; ka < 4; ka++) {
                int r = wid*16 + lrow;
                int c = 2*ka + lsel;
                ldsm4(qfh[ka], sQ + (uint32_t)(r*128 + ((c ^ (r&7)) << 4)));
            }
        }

        const bool active = (kb*64 <= q0 + wid*16 + 15);
        if (active) {
            const uint32_t bK = sStage + (kb & 1) * 32768;
            #pragma unroll
            for (int n = 0; n < 8; n++)
                #pragma unroll
                for (int x = 0; x < 4; x++) S[n][x] = 0.f;

            // ---- S = Q K^T
            #pragma unroll
            for (int ka = 0; ka < 4; ka++) {
                uint32_t qlw[4];
                {
                    int r = wid*16 + lrow;
                    int c = 2*ka + lsel;
                    ldsm4(qlw, sQ + 16384 + (uint32_t)(r*128 + ((c ^ (r&7)) << 4)));
                }
                #pragma unroll
                for (int n16 = 0; n16 < 4; n16++) {
                    int r = n16*16 + lrow;
                    int c = 2*ka + lsel;
                    uint32_t off = (uint32_t)(r*128 + ((c ^ (r&7)) << 4));
                    uint32_t kh4[4], kl4[4];
                    ldsm4(kh4, bK + off);
                    ldsm4(kl4, bK + 8192 + off);
                    uint32_t bh0[2] = { kh4[0], kh4[2] }, bh1[2] = { kh4[1], kh4[3] };
                    uint32_t bl0[2] = { kl4[0], kl4[2] }, bl1[2] = { kl4[1], kl4[3] };
                    mma_bf16(S[2*n16],   qfh[ka], bh0);
                    mma_bf16(S[2*n16],   qlw,     bh0);
                    mma_bf16(S[2*n16],   qfh[ka], bl0);
                    mma_bf16(S[2*n16+1], qfh[ka], bh1);
                    mma_bf16(S[2*n16+1], qlw,     bh1);
                    mma_bf16(S[2*n16+1], qfh[ka], bl1);
                }
            }

            // ---- online softmax (rows r0 = lg, r1 = lg+8 of warp strip)
            const int row0 = q0 + wid*16 + lg;
            const int row1 = row0 + 8;
            #pragma unroll
            for (int n = 0; n < 8; n++)
                #pragma unroll
                for (int x = 0; x < 4; x++) S[n][x] *= 0.125f;
            if (kb >= 2*qb) {
                #pragma unroll
                for (int n = 0; n < 8; n++) {
                    int c0 = kb*64 + n*8 + tg*2;
                    if (c0     > row0) S[n][0] = -1e9f;
                    if (c0 + 1 > row0) S[n][1] = -1e9f;
                    if (c0     > row1) S[n][2] = -1e9f;
                    if (c0 + 1 > row1) S[n][3] = -1e9f;
                }
            }
            float mx0 = -INFINITY, mx1 = -INFINITY;
            #pragma unroll
            for (int n = 0; n < 8; n++) {
                mx0 = fmaxf(mx0, fmaxf(S[n][0], S[n][1]));
                mx1 = fmaxf(mx1, fmaxf(S[n][2], S[n][3]));
            }
            mx0 = fmaxf(mx0, __shfl_xor_sync(0xffffffffu, mx0, 1));
            mx0 = fmaxf(mx0, __shfl_xor_sync(0xffffffffu, mx0, 2));
            mx1 = fmaxf(mx1, __shfl_xor_sync(0xffffffffu, mx1, 1));
            mx1 = fmaxf(mx1, __shfl_xor_sync(0xffffffffu, mx1, 2));
            float mn0 = fmaxf(m0, mx0), mn1 = fmaxf(m1, mx1);
            float sc0 = __expf(m0 - mn0), sc1 = __expf(m1 - mn1);
            m0 = mn0; m1 = mn1;
            float sum0 = 0.f, sum1 = 0.f;
            #pragma unroll
            for (int n = 0; n < 8; n++) {
                S[n][0] = __expf(S[n][0] - mn0);
                S[n][1] = __expf(S[n][1] - mn0);
                S[n][2] = __expf(S[n][2] - mn1);
                S[n][3] = __expf(S[n][3] - mn1);
                sum0 += S[n][0] + S[n][1];
                sum1 += S[n][2] + S[n][3];
            }
            sum0 += __shfl_xor_sync(0xffffffffu, sum0, 1);
            sum0 += __shfl_xor_sync(0xffffffffu, sum0, 2);
            sum1 += __shfl_xor_sync(0xffffffffu, sum1, 1);
            sum1 += __shfl_xor_sync(0xffffffffu, sum1, 2);
            l0 = l0*sc0 + sum0;
            l1 = l1*sc1 + sum1;
            #pragma unroll
            for (int n = 0; n < 8; n++) {
                o[n][0] *= sc0; o[n][1] *= sc0;
                o[n][2] *= sc1; o[n][3] *= sc1;
            }

            // ---- O += P V  (P fragments built in registers from S)
            const uint32_t bV = bK + 16384;
            #pragma unroll
            for (int ka = 0; ka < 4; ka++) {
                uint32_t ah[4], al[4];
                #pragma unroll
                for (int half = 0; half < 2; half++) {
                    const float* s4 = S[2*ka + half];
                    __nv_bfloat16 hA = __float2bfloat16(s4[0]);
                    __nv_bfloat16 hB = __float2bfloat16(s4[1]);
                    __nv_bfloat16 hC = __float2bfloat16(s4[2]);
                    __nv_bfloat16 hD = __float2bfloat16(s4[3]);
                    ah[2*half+0] = pack_bf2(__bfloat162float(hA), __bfloat162float(hB));
                    ah[2*half+1] = pack_bf2(__bfloat162float(hC), __bfloat162float(hD));
                    al[2*half+0] = pack_bf2(s4[0]-__bfloat162float(hA), s4[1]-__bfloat162float(hB));
                    al[2*half+1] = pack_bf2(s4[2]-__bfloat162float(hC), s4[3]-__bfloat162float(hD));
                }
                // note: ah = {a0,a1,a2,a3} with a0=(r, k c), a1=(r+8, k c),
                //       a2=(r, c+8), a3=(r+8, c+8); here k = key within atom.
                #pragma unroll
                for (int ndp = 0; ndp < 4; ndp++) {
                    int r = ka*16 + lrow;
                    int c = 2*ndp + lsel;
                    uint32_t off = (uint32_t)(r*128 + ((c ^ (r&7)) << 4));
                    uint32_t vh4[4], vl4[4];
                    ldsm4t(vh4, bV + off);
                    ldsm4t(vl4, bV + 8192 + off);
                    uint32_t bh0[2] = { vh4[0], vh4[1] }, bh1[2] = { vh4[2], vh4[3] };
                    uint32_t bl0[2] = { vl4[0], vl4[1] }, bl1[2] = { vl4[2], vl4[3] };
                    mma_bf16(o[2*ndp],   ah, bh0);
                    mma_bf16(o[2*ndp],   al, bh0);
                    mma_bf16(o[2*ndp],   ah, bl0);
                    mma_bf16(o[2*ndp+1], ah, bh1);
                    mma_bf16(o[2*ndp+1], al, bh1);
                    mma_bf16(o[2*ndp+1], ah, bl1);
                }
            }
        }
        __syncthreads();
    }

    // ---- epilogue: normalize, split hi/lo, write [bs][h*64+d]
    const float inv0 = 1.0f / l0, inv1 = 1.0f / l1;
    const int b = bh >> 4, h = bh & 15;
    const int r0g = b*Sq + q0 + wid*16 + lg;
    size_t base0 = (size_t)r0g * Dq + h*64 + tg*2;
    size_t base1 = base0 + (size_t)8 * Dq;
    #pragma unroll
    for (int n = 0; n < 8; n++) {
        float v0 = o[n][0]*inv0, v1 = o[n][1]*inv0;
        float v2 = o[n][2]*inv1, v3 = o[n][3]*inv1;
        __nv_bfloat16 h0 = __float2bfloat16(v0), h1 = __float2bfloat16(v1);
        __nv_bfloat16 h2 = __float2bfloat16(v2), h3 = __float2bfloat16(v3);
        *(__nv_bfloat162*)(Oh + base0 + n*8) = __nv_bfloat162(h0, h1);
        *(__nv_bfloat162*)(Oh + base1 + n*8) = __nv_bfloat162(h2, h3);
        *(__nv_bfloat162*)(Ol + base0 + n*8) = __nv_bfloat162(
            __float2bfloat16(v0 - __bfloat162float(h0)),
            __float2bfloat16(v1 - __bfloat162float(h1)));
        *(__nv_bfloat162*)(Ol + base1 + n*8) = __nv_bfloat162(
            __float2bfloat16(v2 - __bfloat162float(h2)),
            __float2bfloat16(v3 - __bfloat162float(h3)));
    }
}

// ---------------------------------------------------------------------------
extern "C" void kernel_launch(void* const* d_in, const int* in_sizes, int n_in,
                              void* d_out, int out_size)
{
    (void)in_sizes; (void)n_in; (void)out_size;
    const float* q  = (const float*)d_in[0];
    const float* k  = (const float*)d_in[1];
    const float* v  = (const float*)d_in[2];
    const float* cs = (const float*)d_in[4];
    const float* sn = (const float*)d_in[5];
    const float* wq = (const float*)d_in[6];
    const float* bq = (const float*)d_in[7];
    const float* wk = (const float*)d_in[8];
    const float* bk = (const float*)d_in[9];
    const float* wv = (const float*)d_in[10];
    const float* bv = (const float*)d_in[11];
    const float* wo = (const float*)d_in[12];
    const float* bo = (const float*)d_in[13];
    const float* qn = (const float*)d_in[14];
    const float* kn = (const float*)d_in[15];
    float* out = (float*)d_out;

    float *pQ, *pK, *pV;
    __nv_bfloat16 *aH, *aL, *wH, *wL, *qh, *ql, *kh, *kl, *vh, *vl;
    cudaGetSymbolAddress((void**)&pQ, g_Q);
    cudaGetSymbolAddress((void**)&pK, g_K);
    cudaGetSymbolAddress((void**)&pV, g_V);
    cudaGetSymbolAddress((void**)&aH, g_actH);
    cudaGetSymbolAddress((void**)&aL, g_actL);
    cudaGetSymbolAddress((void**)&wH, g_wH);
    cudaGetSymbolAddress((void**)&wL, g_wL);
    cudaGetSymbolAddress((void**)&qh, g_Qh);
    cudaGetSymbolAddress((void**)&ql, g_Ql);
    cudaGetSymbolAddress((void**)&kh, g_Kh);
    cudaGetSymbolAddress((void**)&kl, g_Kl);
    cudaGetSymbolAddress((void**)&vh, g_Vh);
    cudaGetSymbolAddress((void**)&vl, g_Vl);

    const int actN4 = Mq*Dq/4, wN4 = Dq*Dq/4;
    const int gsm = 2 * STAGE_B;
    cudaFuncSetAttribute(gemm_tc, cudaFuncAttributeMaxDynamicSharedMemorySize, gsm);
    cudaFuncSetAttribute(flash_attn_tc, cudaFuncAttributeMaxDynamicSharedMemorySize, ATT_SMEM);

    dim3 gg(Dq/128, Mq/128);  // (8, 32)

    split_bf16<<<actN4/256, 256>>>(q, aH, aL, actN4);
    split_bf16<<<wN4/256, 256>>>(wq, wH, wL, wN4);
    gemm_tc<<<gg, 256, gsm>>>(aH, aL, wH, wL, bq, pQ, Mq, Dq, Dq);

    split_bf16<<<actN4/256, 256>>>(k, aH, aL, actN4);
    split_bf16<<<wN4/256, 256>>>(wk, wH, wL, wN4);
    gemm_tc<<<gg, 256, gsm>>>(aH, aL, wH, wL, bk, pK, Mq, Dq, Dq);

    split_bf16<<<actN4/256, 256>>>(v, aH, aL, actN4);
    split_bf16<<<wN4/256, 256>>>(wv, wH, wL, wN4);
    gemm_tc<<<gg, 256, gsm>>>(aH, aL, wH, wL, bv, pV, Mq, Dq, Dq);

    norm_rope_split<<<dim3(Mq*Hq/4, 2), 128>>>(pQ, pK, qh, ql, kh, kl, cs, sn, qn, kn);
    v_split<<<Mq*Dq/4/256, 256>>>(pV, vh, vl);

    flash_attn_tc<<<dim3(Sq/128, Bq*Hq), 256, ATT_SMEM>>>(qh, ql, kh, kl, vh, vl, aH, aL);

    split_bf16<<<wN4/256, 256>>>(wo, wH, wL, wN4);
    gemm_tc<<<gg, 256, gsm>>>(aH, aL, wH, wL, bo, out, Mq, Dq, Dq);
}